// round 11
// baseline (speedup 1.0000x reference)
#include <cuda_runtime.h>
#include <cuda_fp16.h>
#include <cstdint>
#include <math.h>

// ---------------------------------------------------------------------------
// Problem constants
// ---------------------------------------------------------------------------
#define NBATCH 8
#define NCH    64
#define MAPH   96
#define NBR    8
#define BSTR   104
#define BCHS   (BSTR*BSTR)
#define WSETW  18432            // uint32 fragment words per weight set (9*4*4*128)
#define PIXB   144              // bytes per patch pixel (64ch fp16 + 16B pad)
#define WBYTES 73728

// ---------------------------------------------------------------------------
// Device-global scratch (channel-last fp16 activations)
// ---------------------------------------------------------------------------
__device__ __align__(16) __half g_x16[(size_t)NBATCH*MAPH*MAPH*NCH];       // [b][pix][ic]
__device__ __align__(16) __half g_buf1[(size_t)NBR*NBATCH*BCHS*NCH];       // [(br,b)][pix][ic]
__device__ __align__(16) __half g_buf2[(size_t)NBR*NBATCH*BCHS*NCH];
__device__ float  g_bmax[NBR*NBATCH*MAPH*MAPH];
__device__ __align__(16) uint32_t g_w1[8*WSETW];   // fp16 B-fragment images
__device__ __align__(16) uint32_t g_w2[4*WSETW];
__device__ __align__(16) uint32_t g_w3[4*WSETW];
__device__ float g_bias[3*64];

// ---------------------------------------------------------------------------
// Helpers
// ---------------------------------------------------------------------------
__device__ __forceinline__ void rotmap(int k, int A, int B, int& sa, int& sb) {
    switch (k & 3) {
        case 0: sa = A;     sb = B;     break;
        case 1: sa = 2 - B; sb = A;     break;
        case 2: sa = 2 - A; sb = 2 - B; break;
        default: sa = B;    sb = 2 - A; break;
    }
}
__device__ __forceinline__ uint32_t smem_u32(const void* p) {
    uint32_t a;
    asm("{ .reg .u64 t; cvta.to.shared.u64 t, %1; cvt.u32.u64 %0, t; }"
        : "=r"(a) : "l"(p));
    return a;
}
__device__ __forceinline__ void mma_f16(float& c0, float& c1, float& c2, float& c3,
                                        uint32_t a0, uint32_t a1, uint32_t a2, uint32_t a3,
                                        uint32_t b0, uint32_t b1) {
    asm volatile(
        "mma.sync.aligned.m16n8k16.row.col.f32.f16.f16.f32 "
        "{%0,%1,%2,%3}, {%4,%5,%6,%7}, {%8,%9}, {%0,%1,%2,%3};"
        : "+f"(c0), "+f"(c1), "+f"(c2), "+f"(c3)
        : "r"(a0), "r"(a1), "r"(a2), "r"(a3), "r"(b0), "r"(b1));
}
__device__ __forceinline__ void ldmatrix_x4(uint32_t& r0, uint32_t& r1,
                                            uint32_t& r2, uint32_t& r3, uint32_t addr) {
    asm volatile("ldmatrix.sync.aligned.m8n8.x4.shared.b16 {%0,%1,%2,%3}, [%4];"
                 : "=r"(r0), "=r"(r1), "=r"(r2), "=r"(r3) : "r"(addr));
}
__device__ __forceinline__ void cp_async16(uint32_t saddr, const void* gaddr, int srcsz) {
    asm volatile("cp.async.cg.shared.global [%0], [%1], 16, %2;"
                 :: "r"(saddr), "l"(gaddr), "r"(srcsz) : "memory");
}

// ---------------------------------------------------------------------------
// x -> fp16 channel-last transpose: [b][ic][pix] f32 -> [b][pix][ic] f16
// ---------------------------------------------------------------------------
__global__ void cvt_x(const float* __restrict__ x)
{
    __shared__ float t[64][65];
    const int NPB = MAPH * MAPH;                 // 9216
    const int b = blockIdx.x / (NPB / 64);       // 144 tiles per batch
    const int pix0 = (blockIdx.x % (NPB / 64)) * 64;
    const float* src = x + (size_t)b * NCH * NPB;
    for (int i = threadIdx.x; i < 4096; i += 256) {
        int ic = i >> 6, px = i & 63;
        t[px][ic] = src[ic * NPB + pix0 + px];
    }
    __syncthreads();
    __half* dst = g_x16 + ((size_t)b * NPB + pix0) * NCH;
    for (int i = threadIdx.x; i < 4096; i += 256) {
        int px = i >> 6, ic = i & 63;
        dst[px * 64 + ic] = __float2half(t[px][ic]);
    }
}

// ---------------------------------------------------------------------------
// Weight prep: fold BN + rotation + (stage1) channel-roll perm; emit fp16
// B-fragments packed so one LDS.128 serves an nt-pair:
//   word idx e = ((tap*4 + k16)*4 + np)*128 + lane*4 + half*2 + r
//   nt = np*2 + half; halves = W[oc = nt*8 + lane/4]
//                              [ic = k16*16 + 2*(lane%4) + 8r + {0,1}]
// ---------------------------------------------------------------------------
__global__ void prep_kernel(
    const float* __restrict__ dcn_w, const float* __restrict__ dcn_b,
    const float* __restrict__ c2w,   const float* __restrict__ c2b,
    const float* __restrict__ c3w,   const float* __restrict__ c3b,
    const float* __restrict__ gam,   const float* __restrict__ bet,
    const float* __restrict__ mu,    const float* __restrict__ va)
{
    int id = blockIdx.x * blockDim.x + threadIdx.x;
    const int W1N = 8 * WSETW, W2N = 4 * WSETW;

    if (id < W1N + 2 * W2N) {
        int setBase;
        uint32_t* dst;
        const float* src;
        int bnOff;
        if (id < W1N)            { dst = g_w1; src = dcn_w; bnOff = 0;   setBase = id; }
        else if (id < W1N + W2N) { dst = g_w2; src = c2w;   bnOff = 64;  setBase = id - W1N; }
        else                     { dst = g_w3; src = c3w;   bnOff = 128; setBase = id - W1N - W2N; }
        int set = setBase / WSETW;
        int e   = setBase % WSETW;
        int r    = e & 1;
        int half = (e >> 1) & 1;
        int lane = (e >> 2) & 31;
        int np   = (e >> 7) & 3;
        int k16  = (e >> 9) & 3;
        int tap  = e >> 11;            // 0..8
        int nt = np * 2 + half;
        int oc  = nt * 8 + (lane >> 2);
        int ic0 = k16 * 16 + 2 * (lane & 3) + 8 * r;
        int sa, sb; rotmap(set & 3, tap / 3, tap % 3, sa, sb);
        float scale = gam[bnOff + oc] * rsqrtf(va[bnOff + oc] + 1e-5f);
        int sc0 = (bnOff == 0) ? ((ic0 + 8 * set) & 63) : ic0;
        int sc1 = (bnOff == 0) ? ((ic0 + 1 + 8 * set) & 63) : (ic0 + 1);
        float v0 = src[((oc * 64 + sc0) * 3 + sa) * 3 + sb] * scale;
        float v1 = src[((oc * 64 + sc1) * 3 + sa) * 3 + sb] * scale;
        uint32_t w = (uint32_t)__half_as_ushort(__float2half(v0))
                   | ((uint32_t)__half_as_ushort(__float2half(v1)) << 16);
        dst[setBase] = w;
        return;
    }
    id -= W1N + 2 * W2N;
    if (id < 192) {
        int s = id / 64, oc = id & 63;
        float scale = gam[s * 64 + oc] * rsqrtf(va[s * 64 + oc] + 1e-5f);
        const float* cb = (s == 0) ? dcn_b : ((s == 1) ? c2b : c3b);
        g_bias[id] = cb[oc] * scale + bet[s * 64 + oc] - mu[s * 64 + oc] * scale;
    }
}

// ---------------------------------------------------------------------------
// Async patch load into one buffer slot (zfill OOB). Templated on R,C so
// the / C becomes a multiply.
// ---------------------------------------------------------------------------
template<int R, int C>
__device__ __forceinline__ void load_patch(
    uint32_t dstU, const uint4* __restrict__ srcV,
    int rowBase, int colBase, int pad, int inValid, int srcStride, int tid)
{
    #pragma unroll 2
    for (int i = tid; i < R * C * 8; i += 256) {
        int w   = i & 7;
        int pix = i >> 3;
        int r = pix / C;
        int c = pix - r * C;
        int gy = rowBase + r - pad;
        int gx = colBase + c - pad;
        bool ok = ((unsigned)gy < (unsigned)inValid) & ((unsigned)gx < (unsigned)inValid);
        const void* gp = ok ? (const void*)(srcV + (size_t)(gy * srcStride + gx) * 8 + w)
                            : (const void*)srcV;
        cp_async16(dstU + pix * PIXB + w * 16, gp, ok ? 16 : 0);
    }
}

// ---------------------------------------------------------------------------
// Conv kernel: fp16 mma.sync.m16n8k16 implicit GEMM with double-buffered
// cp.async patch pipeline.
// Block = 256 threads = 8 warps (warp w = tile row w). 1 CTA/SM.
// CTA tile = 8 rows x 32 cols = 256 px. Warp tile = 32 px x 64 oc
// (mtc = 2 m16 col-groups, nt = 8). K = 576 = 9 taps x 4 k16.
// Each CTA covers 2 rowTiles x colTiles, prefetching tile t+1 during GEMM t.
// ---------------------------------------------------------------------------
template<int D, int STAGE>
__global__ void __launch_bounds__(256, 1)
conv_mma()
{
    constexpr int R = 8 + 2 * D;          // patch rows
    constexpr int C = 32 + 2 * D;         // patch cols
    constexpr int NPIX = R * C;
    constexpr int PATB = NPIX * PIXB;

    extern __shared__ char sm[];
    uint32_t* sW    = (uint32_t*)sm;                      // 73728B
    float*    sBias = (float*)(sm + WBYTES + 2 * PATB);   // 64

    const int tid  = threadIdx.x;
    const int lane = tid & 31;
    const int wid  = tid >> 5;            // tile row 0..7

    const int br = blockIdx.z;
    const int b  = blockIdx.y;
    const int odd = br & 1;

    int pad, inValid, outH;
    if (STAGE == 1)      { pad = odd ? 5 : 1; inValid = 96;             outH = odd ? 104 : 96; }
    else if (STAGE == 2) { pad = odd ? 0 : 2; inValid = odd ? 104 : 96; outH = odd ? 100 : 96; }
    else                 { pad = odd ? 0 : 2; inValid = odd ? 100 : 96; outH = 96; }
    const int outW = outH;
    const int rowTiles = (outH + 7) >> 3;
    const int colTiles = (outW + 31) >> 5;
    const int rt0 = blockIdx.x * 2;
    const int nRT = (rowTiles - rt0 < 2) ? (rowTiles - rt0) : 2;
    if (nRT <= 0) return;
    const int nT = nRT * colTiles;

    const int srcStride = (STAGE == 1) ? MAPH : BSTR;
    const __half* inp = (STAGE == 1) ? (g_x16 + (size_t)b * MAPH * MAPH * NCH)
                       : (STAGE == 2) ? (g_buf1 + (size_t)(br * NBATCH + b) * BCHS * NCH)
                                      : (g_buf2 + (size_t)(br * NBATCH + b) * BCHS * NCH);
    __half* outp = ((STAGE == 1) ? g_buf1 : g_buf2)
                   + (size_t)(br * NBATCH + b) * BCHS * NCH;
    const uint32_t* wsrc = (STAGE == 1) ? (g_w1 + br * WSETW)
                          : (STAGE == 2) ? (g_w2 + (br & 3) * WSETW)
                                         : (g_w3 + (br & 3) * WSETW);

    // ---- stage weights (fragment words, linear copy) + bias ----
    {
        uint4* wd = (uint4*)sW;
        const uint4* ws = (const uint4*)wsrc;
        #pragma unroll 4
        for (int i = tid; i < WSETW / 4; i += 256) wd[i] = ws[i];
        if (tid < 64) sBias[tid] = g_bias[(STAGE - 1) * 64 + tid];
    }

    const int g  = lane >> 2;
    const int t4 = lane & 3;

    const uint32_t smU = smem_u32(sm);
    const uint32_t bufU[2] = { smU + WBYTES, smU + WBYTES + PATB };
    // ldmatrix per-lane offset within a buffer: warp row, pixel col, k-half
    const uint32_t aWarp = (uint32_t)((wid * C + (lane & 15)) * PIXB + (lane >> 4) * 16);

    const uint4* srcV = (const uint4*)inp;
    float* bm = g_bmax + (size_t)(br * NBATCH + b) * MAPH * MAPH;

    // ---- pipeline: preload tile 0 ----
    int curRT = rt0, curCT = 0;
    load_patch<R, C>(bufU[0], srcV, curRT * 8, 0, pad, inValid, srcStride, tid);
    asm volatile("cp.async.commit_group;" ::: "memory");

    int nxtRT = curRT, nxtCT = 1;
    if (nxtCT == colTiles) { nxtCT = 0; nxtRT++; }

    for (int t = 0; t < nT; t++) {
        const int slot = t & 1;
        const int rowBase = curRT * 8;
        const int colBase = curCT * 32;

        if (t + 1 < nT) {
            load_patch<R, C>(bufU[slot ^ 1], srcV, nxtRT * 8, nxtCT * 32,
                             pad, inValid, srcStride, tid);
            asm volatile("cp.async.commit_group;" ::: "memory");
            asm volatile("cp.async.wait_group 1;" ::: "memory");
        } else {
            asm volatile("cp.async.wait_group 0;" ::: "memory");
        }
        __syncthreads();

        // ---- GEMM: 256px x 64oc x 576; warp = 32px (1 row) x 64oc ----
        float acc[2][8][4];
        #pragma unroll
        for (int mtc = 0; mtc < 2; mtc++)
            #pragma unroll
            for (int nt = 0; nt < 8; nt++)
                #pragma unroll
                for (int q = 0; q < 4; q++) acc[mtc][nt][q] = 0.f;

        const uint32_t aBase = bufU[slot] + aWarp;

        #pragma unroll 1
        for (int tap = 0; tap < 9; tap++) {
            const int dy = (tap / 3) * D, dx = (tap % 3) * D;
            const uint32_t aT = aBase + (dy * C + dx) * PIXB;

            #pragma unroll
            for (int k16 = 0; k16 < 4; k16++) {
                uint32_t a[2][4];
                ldmatrix_x4(a[0][0], a[0][1], a[0][2], a[0][3], aT + k16 * 32);
                ldmatrix_x4(a[1][0], a[1][1], a[1][2], a[1][3],
                            aT + 16 * PIXB + k16 * 32);
                const uint4* pB = (const uint4*)sW + (tap * 16 + k16 * 4) * 32 + lane;
                #pragma unroll
                for (int np = 0; np < 4; np++) {
                    uint4 bb = pB[np * 32];
                    #pragma unroll
                    for (int mtc = 0; mtc < 2; mtc++) {
                        mma_f16(acc[mtc][2*np][0], acc[mtc][2*np][1],
                                acc[mtc][2*np][2], acc[mtc][2*np][3],
                                a[mtc][0], a[mtc][1], a[mtc][2], a[mtc][3], bb.x, bb.y);
                        mma_f16(acc[mtc][2*np+1][0], acc[mtc][2*np+1][1],
                                acc[mtc][2*np+1][2], acc[mtc][2*np+1][3],
                                a[mtc][0], a[mtc][1], a[mtc][2], a[mtc][3], bb.z, bb.w);
                    }
                }
            }
        }

        // ---- epilogue (warp owns all 64 oc of its 32 pixels) ----
        const int oy = rowBase + wid;
        if (STAGE < 3) {
            if (oy < outH) {
                #pragma unroll
                for (int mtc = 0; mtc < 2; mtc++) {
                    const int ox0 = colBase + mtc * 16 + g;
                    const int ox1 = ox0 + 8;
                    #pragma unroll
                    for (int nt = 0; nt < 8; nt++) {
                        const int oc = nt * 8 + 2 * t4;
                        const float b0 = sBias[oc], b1 = sBias[oc + 1];
                        if (ox0 < outW) {
                            float2 f = make_float2(fmaxf(acc[mtc][nt][0] + b0, 0.f),
                                                   fmaxf(acc[mtc][nt][1] + b1, 0.f));
                            *(__half2*)(outp + (size_t)(oy * BSTR + ox0) * 64 + oc) =
                                __float22half2_rn(f);
                        }
                        if (ox1 < outW) {
                            float2 f = make_float2(fmaxf(acc[mtc][nt][2] + b0, 0.f),
                                                   fmaxf(acc[mtc][nt][3] + b1, 0.f));
                            *(__half2*)(outp + (size_t)(oy * BSTR + ox1) * 64 + oc) =
                                __float22half2_rn(f);
                        }
                    }
                }
            }
        } else {
            #pragma unroll
            for (int mtc = 0; mtc < 2; mtc++) {
                float v0 = 0.f, v1 = 0.f;
                #pragma unroll
                for (int nt = 0; nt < 8; nt++) {
                    const int oc = nt * 8 + 2 * t4;
                    const float b0 = sBias[oc], b1 = sBias[oc + 1];
                    v0 = fmaxf(v0, fmaxf(acc[mtc][nt][0] + b0, acc[mtc][nt][1] + b1));
                    v1 = fmaxf(v1, fmaxf(acc[mtc][nt][2] + b0, acc[mtc][nt][3] + b1));
                }
                v0 = fmaxf(v0, __shfl_xor_sync(0xFFFFFFFF, v0, 1));
                v0 = fmaxf(v0, __shfl_xor_sync(0xFFFFFFFF, v0, 2));
                v1 = fmaxf(v1, __shfl_xor_sync(0xFFFFFFFF, v1, 1));
                v1 = fmaxf(v1, __shfl_xor_sync(0xFFFFFFFF, v1, 2));
                if (t4 == 0 && oy < MAPH) {
                    const int ox0 = colBase + mtc * 16 + g;
                    if (ox0 < MAPH)     bm[oy * MAPH + ox0]     = v0;
                    if (ox0 + 8 < MAPH) bm[oy * MAPH + ox0 + 8] = v1;
                }
            }
        }

        __syncthreads();   // reads of this slot done before it is refilled at t+2

        curRT = nxtRT; curCT = nxtCT;
        if (++nxtCT == colTiles) { nxtCT = 0; nxtRT++; }
    }
}

// ---------------------------------------------------------------------------
// Cross-branch max + sigmoid + clip
// ---------------------------------------------------------------------------
__global__ void final_k(float* __restrict__ out)
{
    int i = blockIdx.x * blockDim.x + threadIdx.x;
    const int NPB = MAPH * MAPH;
    if (i >= NBATCH * NPB) return;
    int b = i / NPB, p = i - b * NPB;
    float m = g_bmax[b * NPB + p];
    #pragma unroll
    for (int br = 1; br < NBR; br++)
        m = fmaxf(m, g_bmax[(br * NBATCH + b) * NPB + p]);
    float s = 1.f / (1.f + expf(-m));
    out[i] = fminf(fmaxf(s, 0.0001f), 0.9999f);
}

// ---------------------------------------------------------------------------
// Launch
// ---------------------------------------------------------------------------
extern "C" void kernel_launch(void* const* d_in, const int* in_sizes, int n_in,
                              void* d_out, int out_size)
{
    const float* x     = (const float*)d_in[0];
    const float* dcn_w = (const float*)d_in[2];
    const float* dcn_b = (const float*)d_in[3];
    const float* c2w   = (const float*)d_in[4];
    const float* c2b   = (const float*)d_in[5];
    const float* c3w   = (const float*)d_in[6];
    const float* c3b   = (const float*)d_in[7];
    const float* gam   = (const float*)d_in[8];
    const float* bet   = (const float*)d_in[9];
    const float* mu    = (const float*)d_in[10];
    const float* va    = (const float*)d_in[11];

    constexpr int SMEM_D1 = WBYTES + 2 * (10 * 34 * PIXB) + 64 * 4;  // 171,904
    constexpr int SMEM_D2 = WBYTES + 2 * (12 * 36 * PIXB) + 64 * 4;  // 198,400

    cudaFuncSetAttribute((const void*)conv_mma<1, 1>,
                         cudaFuncAttributeMaxDynamicSharedMemorySize, SMEM_D1);
    cudaFuncSetAttribute((const void*)conv_mma<2, 2>,
                         cudaFuncAttributeMaxDynamicSharedMemorySize, SMEM_D2);
    cudaFuncSetAttribute((const void*)conv_mma<2, 3>,
                         cudaFuncAttributeMaxDynamicSharedMemorySize, SMEM_D2);

    cvt_x<<<NBATCH * (MAPH * MAPH / 64), 256>>>(x);

    const int prepN = 16 * WSETW + 192;
    prep_kernel<<<(prepN + 255) / 256, 256>>>(dcn_w, dcn_b, c2w, c2b, c3w, c3b,
                                              gam, bet, mu, va);

    // grid.x = ceil(rowTiles/2): stage1 odd 13 -> 7; stage2 odd 13 -> 7; stage3 12 -> 6
    conv_mma<1, 1><<<dim3(7, NBATCH, NBR), 256, SMEM_D1>>>();
    conv_mma<2, 2><<<dim3(7, NBATCH, NBR), 256, SMEM_D2>>>();
    conv_mma<2, 3><<<dim3(6, NBATCH, NBR), 256, SMEM_D2>>>();

    final_k<<<(NBATCH * MAPH * MAPH + 255) / 256, 256>>>((float*)d_out);
}

// round 12
// speedup vs baseline: 1.0904x; 1.0904x over previous
#include <cuda_runtime.h>
#include <cuda_fp16.h>
#include <cuda.h>
#include <cstdint>
#include <math.h>

#define NBATCH 8
#define NCH    64
#define MAPH   96
#define NBR    8
#define BSTR   104
#define BCHS   (BSTR*BSTR)
#define WSETW  18432
#define WBYTES 73728
#define TILER  24
#define TILEC  16

// channel-last fp16 activations, pixel stride 128B. Zero-init halos are
// load-bearing: TMA reads of never-written regions must return 0.
__device__ __align__(1024) __half g_x16[(size_t)NBATCH*MAPH*MAPH*NCH];
__device__ __align__(1024) __half g_buf1[(size_t)NBR*NBATCH*BCHS*NCH];
__device__ __align__(1024) __half g_buf2[(size_t)NBR*NBATCH*BCHS*NCH];
__device__ float  g_bmax[NBR*NBATCH*MAPH*MAPH];
__device__ __align__(16) uint32_t g_w1[8*WSETW];
__device__ __align__(16) uint32_t g_w2[4*WSETW];
__device__ __align__(16) uint32_t g_w3[4*WSETW];
__device__ float g_bias[3*64];

__device__ __forceinline__ void rotmap(int k, int A, int B, int& sa, int& sb) {
    switch (k & 3) {
        case 0: sa = A;     sb = B;     break;
        case 1: sa = 2 - B; sb = A;     break;
        case 2: sa = 2 - A; sb = 2 - B; break;
        default: sa = B;    sb = 2 - A; break;
    }
}
__device__ __forceinline__ uint32_t smem_u32(const void* p) {
    uint32_t a;
    asm("{ .reg .u64 t; cvta.to.shared.u64 t, %1; cvt.u32.u64 %0, t; }"
        : "=r"(a) : "l"(p));
    return a;
}
__device__ __forceinline__ void mma_f16(float& c0, float& c1, float& c2, float& c3,
                                        uint32_t a0, uint32_t a1, uint32_t a2, uint32_t a3,
                                        uint32_t b0, uint32_t b1) {
    asm volatile(
        "mma.sync.aligned.m16n8k16.row.col.f32.f16.f16.f32 "
        "{%0,%1,%2,%3}, {%4,%5,%6,%7}, {%8,%9}, {%0,%1,%2,%3};"
        : "+f"(c0), "+f"(c1), "+f"(c2), "+f"(c3)
        : "r"(a0), "r"(a1), "r"(a2), "r"(a3), "r"(b0), "r"(b1));
}
__device__ __forceinline__ void ldmatrix_x4(uint32_t& r0, uint32_t& r1,
                                            uint32_t& r2, uint32_t& r3, uint32_t addr) {
    asm volatile("ldmatrix.sync.aligned.m8n8.x4.shared.b16 {%0,%1,%2,%3}, [%4];"
                 : "=r"(r0), "=r"(r1), "=r"(r2), "=r"(r3) : "r"(addr));
}
__device__ __forceinline__ void tma4d(uint32_t dst, const CUtensorMap* m,
                                      int cx, int cy, int img, uint32_t mbar) {
    asm volatile(
        "cp.async.bulk.tensor.4d.shared::cta.global.tile.mbarrier::complete_tx::bytes "
        "[%0], [%1, {%2, %3, %4, %5}], [%6];"
        :: "r"(dst), "l"(m), "r"(0), "r"(cx), "r"(cy), "r"(img), "r"(mbar)
        : "memory");
}
#define MBAR_INIT(a, n) \
    asm volatile("mbarrier.init.shared.b64 [%0], %1;" :: "r"(a), "r"(n) : "memory")
#define MBAR_EXPECT(a, bytes) \
    asm volatile("mbarrier.arrive.expect_tx.shared.b64 _, [%0], %1;" \
                 :: "r"(a), "r"(bytes) : "memory")
__device__ __forceinline__ void mbar_wait(uint32_t a, uint32_t ph) {
    uint32_t done;
    asm volatile("{\n\t.reg .pred p;\n\t"
        "mbarrier.try_wait.parity.acquire.cta.shared::cta.b64 p, [%1], %2;\n\t"
        "selp.b32 %0, 1, 0, p;\n\t}" : "=r"(done) : "r"(a), "r"(ph) : "memory");
    if (!done) {
        asm volatile("{\n\t.reg .pred P1;\n\t"
            "WL_%=:\n\t"
            "mbarrier.try_wait.parity.acquire.cta.shared::cta.b64 P1, [%0], %1, 0x989680;\n\t"
            "@P1 bra.uni WD_%=;\n\t"
            "bra.uni WL_%=;\n\t"
            "WD_%=:\n\t}" :: "r"(a), "r"(ph) : "memory");
    }
}

// ---------------------------------------------------------------------------
__global__ void cvt_x(const float* __restrict__ x)
{
    __shared__ float t[64][65];
    const int NPB = MAPH * MAPH;
    const int b = blockIdx.x / (NPB / 64);
    const int pix0 = (blockIdx.x % (NPB / 64)) * 64;
    const float* src = x + (size_t)b * NCH * NPB;
    for (int i = threadIdx.x; i < 4096; i += 256) {
        int ic = i >> 6, px = i & 63;
        t[px][ic] = src[ic * NPB + pix0 + px];
    }
    __syncthreads();
    __half* dst = g_x16 + ((size_t)b * NPB + pix0) * NCH;
    for (int i = threadIdx.x; i < 4096; i += 256) {
        int px = i >> 6, ic = i & 63;
        dst[px * 64 + ic] = __float2half(t[px][ic]);
    }
}

// ---------------------------------------------------------------------------
__global__ void prep_kernel(
    const float* __restrict__ dcn_w, const float* __restrict__ dcn_b,
    const float* __restrict__ c2w,   const float* __restrict__ c2b,
    const float* __restrict__ c3w,   const float* __restrict__ c3b,
    const float* __restrict__ gam,   const float* __restrict__ bet,
    const float* __restrict__ mu,    const float* __restrict__ va)
{
    int id = blockIdx.x * blockDim.x + threadIdx.x;
    const int W1N = 8 * WSETW, W2N = 4 * WSETW;

    if (id < W1N + 2 * W2N) {
        int setBase;
        uint32_t* dst;
        const float* src;
        int bnOff;
        if (id < W1N)            { dst = g_w1; src = dcn_w; bnOff = 0;   setBase = id; }
        else if (id < W1N + W2N) { dst = g_w2; src = c2w;   bnOff = 64;  setBase = id - W1N; }
        else                     { dst = g_w3; src = c3w;   bnOff = 128; setBase = id - W1N - W2N; }
        int set = setBase / WSETW;
        int e   = setBase % WSETW;
        int r    = e & 1;
        int half = (e >> 1) & 1;
        int lane = (e >> 2) & 31;
        int np   = (e >> 7) & 3;
        int k16  = (e >> 9) & 3;
        int tap  = e >> 11;
        int nt = np * 2 + half;
        int oc  = nt * 8 + (lane >> 2);
        int ic0 = k16 * 16 + 2 * (lane & 3) + 8 * r;
        int sa, sb; rotmap(set & 3, tap / 3, tap % 3, sa, sb);
        float scale = gam[bnOff + oc] * rsqrtf(va[bnOff + oc] + 1e-5f);
        int sc0 = (bnOff == 0) ? ((ic0 + 8 * set) & 63) : ic0;
        int sc1 = (bnOff == 0) ? ((ic0 + 1 + 8 * set) & 63) : (ic0 + 1);
        float v0 = src[((oc * 64 + sc0) * 3 + sa) * 3 + sb] * scale;
        float v1 = src[((oc * 64 + sc1) * 3 + sa) * 3 + sb] * scale;
        dst[setBase] = (uint32_t)__half_as_ushort(__float2half(v0))
                     | ((uint32_t)__half_as_ushort(__float2half(v1)) << 16);
        return;
    }
    id -= W1N + 2 * W2N;
    if (id < 192) {
        int s = id / 64, oc = id & 63;
        float scale = gam[s * 64 + oc] * rsqrtf(va[s * 64 + oc] + 1e-5f);
        const float* cb = (s == 0) ? dcn_b : ((s == 1) ? c2b : c3b);
        g_bias[id] = cb[oc] * scale + bet[s * 64 + oc] - mu[s * 64 + oc] * scale;
    }
}

// ---------------------------------------------------------------------------
// Conv: fp16 mma implicit GEMM, TMA-fed double-buffered patches (SW128).
// 256 thr = 8 warps; warp w owns tile rows 3w..3w+2 (mt=0..2) x 64 oc.
// CTA tile 24x16; CTA iterates colTiles with 2-deep TMA pipeline.
// ---------------------------------------------------------------------------
template<int D, int STAGE>
__global__ void __launch_bounds__(256, 1)
conv_mma(const __grid_constant__ CUtensorMap tmap)
{
    constexpr int R = TILER + 2 * D;
    constexpr int C = TILEC + 2 * D;
    constexpr int PATB = R * C * 128;
    constexpr int PATB_AL = (PATB + 1023) & ~1023;
    constexpr int OFF_B0 = WBYTES;
    constexpr int OFF_B1 = WBYTES + PATB_AL;
    constexpr int OFF_MB = WBYTES + 2 * PATB_AL;
    constexpr int OFF_BIAS = OFF_MB + 16;

    extern __shared__ char sm[];
    const uint32_t raw = smem_u32(sm);
    const uint32_t base = (raw + 1023) & ~1023u;
    char* smc = sm + (base - raw);
    uint32_t* sW = (uint32_t*)smc;
    float* sBias = (float*)(smc + OFF_BIAS);

    const int tid  = threadIdx.x;
    const int lane = tid & 31;
    const int wid  = tid >> 5;

    const int br = blockIdx.z;
    const int b  = blockIdx.y;
    const int odd = br & 1;

    int pad, outH;
    if (STAGE == 1)      { pad = odd ? 5 : 1; outH = odd ? 104 : 96; }
    else if (STAGE == 2) { pad = odd ? 0 : 2; outH = odd ? 100 : 96; }
    else                 { pad = odd ? 0 : 2; outH = 96; }
    const int outW = outH;
    const int rowTiles = (outH + TILER - 1) / TILER;
    const int colTiles = (outW + TILEC - 1) / TILEC;
    const int rowTile = blockIdx.x;
    if (rowTile >= rowTiles) return;

    const int img = (STAGE == 1) ? b : (br * NBATCH + b);
    __half* outp = ((STAGE == 1) ? g_buf1 : g_buf2)
                   + (size_t)(br * NBATCH + b) * BCHS * NCH;
    const uint32_t* wsrc = (STAGE == 1) ? (g_w1 + br * WSETW)
                          : (STAGE == 2) ? (g_w2 + (br & 3) * WSETW)
                                         : (g_w3 + (br & 3) * WSETW);

    // weights + bias + mbarriers
    {
        uint4* wd = (uint4*)sW;
        const uint4* ws = (const uint4*)wsrc;
        #pragma unroll 4
        for (int i = tid; i < WSETW / 4; i += 256) wd[i] = ws[i];
        if (tid < 64) sBias[tid] = g_bias[(STAGE - 1) * 64 + tid];
        if (tid == 0) { MBAR_INIT(base + OFF_MB, 1); MBAR_INIT(base + OFF_MB + 8, 1); }
    }
    __syncthreads();

    const int g  = lane >> 2;
    const int t4 = lane & 3;
    const int rowBase = rowTile * TILER;
    const uint32_t bufU[2] = { base + OFF_B0, base + OFF_B1 };
    const uint32_t mbU[2]  = { base + OFF_MB, base + OFF_MB + 8 };

    // per-lane A addressing: pixel col = lane&15, k-half = lane>>4
    const int ccol = lane & 15;
    const int khalf16 = (lane >> 4) * 16;
    int pixBase[3];
    #pragma unroll
    for (int mt = 0; mt < 3; mt++) pixBase[mt] = (wid * 3 + mt) * C + ccol;

    float* bm = g_bmax + (size_t)(br * NBATCH + b) * MAPH * MAPH;
    uint32_t ph[2] = {0, 0};

    // preload tile 0
    if (tid == 0) {
        MBAR_EXPECT(mbU[0], PATB);
        tma4d(bufU[0], &tmap, 0 - pad, rowBase - pad, img, mbU[0]);
    }

    for (int t = 0; t < colTiles; t++) {
        const int s = t & 1;
        const int colBase = t * TILEC;

        if (t + 1 < colTiles && tid == 0) {
            MBAR_EXPECT(mbU[s ^ 1], PATB);
            tma4d(bufU[s ^ 1], &tmap, (t + 1) * TILEC - pad, rowBase - pad, img, mbU[s ^ 1]);
        }
        mbar_wait(mbU[s], ph[s]); ph[s] ^= 1;

        float acc[3][8][4];
        #pragma unroll
        for (int mt = 0; mt < 3; mt++)
            #pragma unroll
            for (int nt = 0; nt < 8; nt++)
                #pragma unroll
                for (int q = 0; q < 4; q++) acc[mt][nt][q] = 0.f;

        const uint32_t bU = bufU[s];

        #pragma unroll 1
        for (int tap = 0; tap < 9; tap++) {
            const int dyD = (tap / 3) * D, dxD = (tap % 3) * D;
            uint32_t aP[3], swm[3];
            #pragma unroll
            for (int mt = 0; mt < 3; mt++) {
                const int p = pixBase[mt] + dyD * C + dxD;
                aP[mt] = bU + (uint32_t)(p << 7);
                swm[mt] = (uint32_t)((p & 7) << 4);
            }
            const uint4* pB = (const uint4*)sW + (tap * 16) * 32 + lane;

            #pragma unroll
            for (int k16 = 0; k16 < 4; k16++) {
                const uint32_t kofs = k16 * 32 + khalf16;
                uint32_t a[3][4];
                #pragma unroll
                for (int mt = 0; mt < 3; mt++)
                    ldmatrix_x4(a[mt][0], a[mt][1], a[mt][2], a[mt][3],
                                aP[mt] + (kofs ^ swm[mt]));
                const uint4* pBk = pB + (k16 * 4) * 32;
                #pragma unroll
                for (int np = 0; np < 4; np++) {
                    uint4 bb = pBk[np * 32];
                    #pragma unroll
                    for (int mt = 0; mt < 3; mt++) {
                        mma_f16(acc[mt][2*np][0], acc[mt][2*np][1],
                                acc[mt][2*np][2], acc[mt][2*np][3],
                                a[mt][0], a[mt][1], a[mt][2], a[mt][3], bb.x, bb.y);
                        mma_f16(acc[mt][2*np+1][0], acc[mt][2*np+1][1],
                                acc[mt][2*np+1][2], acc[mt][2*np+1][3],
                                a[mt][0], a[mt][1], a[mt][2], a[mt][3], bb.z, bb.w);
                    }
                }
            }
        }

        // epilogue: warp owns all 64 oc of its 48 pixels
        if (STAGE < 3) {
            #pragma unroll
            for (int mt = 0; mt < 3; mt++) {
                const int oy = rowBase + wid * 3 + mt;
                if (oy >= outH) continue;
                const int ox0 = colBase + g;
                const int ox1 = ox0 + 8;
                #pragma unroll
                for (int nt = 0; nt < 8; nt++) {
                    const int oc = nt * 8 + 2 * t4;
                    const float b0 = sBias[oc], b1 = sBias[oc + 1];
                    if (ox0 < outW) {
                        float2 f = make_float2(fmaxf(acc[mt][nt][0] + b0, 0.f),
                                               fmaxf(acc[mt][nt][1] + b1, 0.f));
                        *(__half2*)(outp + (size_t)(oy * BSTR + ox0) * 64 + oc) =
                            __float22half2_rn(f);
                    }
                    if (ox1 < outW) {
                        float2 f = make_float2(fmaxf(acc[mt][nt][2] + b0, 0.f),
                                               fmaxf(acc[mt][nt][3] + b1, 0.f));
                        *(__half2*)(outp + (size_t)(oy * BSTR + ox1) * 64 + oc) =
                            __float22half2_rn(f);
                    }
                }
            }
        } else {
            #pragma unroll
            for (int mt = 0; mt < 3; mt++) {
                const int oy = rowBase + wid * 3 + mt;
                float v0 = 0.f, v1 = 0.f;
                #pragma unroll
                for (int nt = 0; nt < 8; nt++) {
                    const int oc = nt * 8 + 2 * t4;
                    const float b0 = sBias[oc], b1 = sBias[oc + 1];
                    v0 = fmaxf(v0, fmaxf(acc[mt][nt][0] + b0, acc[mt][nt][1] + b1));
                    v1 = fmaxf(v1, fmaxf(acc[mt][nt][2] + b0, acc[mt][nt][3] + b1));
                }
                v0 = fmaxf(v0, __shfl_xor_sync(0xFFFFFFFF, v0, 1));
                v0 = fmaxf(v0, __shfl_xor_sync(0xFFFFFFFF, v0, 2));
                v1 = fmaxf(v1, __shfl_xor_sync(0xFFFFFFFF, v1, 1));
                v1 = fmaxf(v1, __shfl_xor_sync(0xFFFFFFFF, v1, 2));
                if (t4 == 0 && oy < MAPH) {
                    const int ox0 = colBase + g;
                    if (ox0 < MAPH)     bm[oy * MAPH + ox0]     = v0;
                    if (ox0 + 8 < MAPH) bm[oy * MAPH + ox0 + 8] = v1;
                }
            }
        }

        __syncthreads();   // slot s fully read before refill at t+2
    }
}

// ---------------------------------------------------------------------------
__global__ void final_k(float* __restrict__ out)
{
    int i = blockIdx.x * blockDim.x + threadIdx.x;
    const int NPB = MAPH * MAPH;
    if (i >= NBATCH * NPB) return;
    int b = i / NPB, p = i - b * NPB;
    float m = g_bmax[b * NPB + p];
    #pragma unroll
    for (int br = 1; br < NBR; br++)
        m = fmaxf(m, g_bmax[(br * NBATCH + b) * NPB + p]);
    float s = 1.f / (1.f + expf(-m));
    out[i] = fminf(fmaxf(s, 0.0001f), 0.9999f);
}

// ---------------------------------------------------------------------------
// Host: tensor-map encoding + launch
// ---------------------------------------------------------------------------
typedef CUresult (*EncFn)(CUtensorMap*, CUtensorMapDataType, cuuint32_t, void*,
                          const cuuint64_t*, const cuuint64_t*, const cuuint32_t*,
                          const cuuint32_t*, CUtensorMapInterleave, CUtensorMapSwizzle,
                          CUtensorMapL2promotion, CUtensorMapFloatOOBfill);

static void encode_map(EncFn enc, CUtensorMap* m, void* ptr,
                       int dimX, int dimY, int nImg, int strideX,
                       int boxC, int boxR)
{
    cuuint64_t dims[4]    = { 128, (cuuint64_t)dimX, (cuuint64_t)dimY, (cuuint64_t)nImg };
    cuuint64_t strides[3] = { 128, (cuuint64_t)strideX * 128,
                              (cuuint64_t)strideX * (cuuint64_t)dimY * 128 };
    cuuint32_t box[4]     = { 128, (cuuint32_t)boxC, (cuuint32_t)boxR, 1 };
    cuuint32_t es[4]      = { 1, 1, 1, 1 };
    enc(m, CU_TENSOR_MAP_DATA_TYPE_UINT8, 4, ptr, dims, strides, box, es,
        CU_TENSOR_MAP_INTERLEAVE_NONE, CU_TENSOR_MAP_SWIZZLE_128B,
        CU_TENSOR_MAP_L2_PROMOTION_L2_128B, CU_TENSOR_MAP_FLOAT_OOB_FILL_NONE);
}

extern "C" void kernel_launch(void* const* d_in, const int* in_sizes, int n_in,
                              void* d_out, int out_size)
{
    const float* x     = (const float*)d_in[0];
    const float* dcn_w = (const float*)d_in[2];
    const float* dcn_b = (const float*)d_in[3];
    const float* c2w   = (const float*)d_in[4];
    const float* c2b   = (const float*)d_in[5];
    const float* c3w   = (const float*)d_in[6];
    const float* c3b   = (const float*)d_in[7];
    const float* gam   = (const float*)d_in[8];
    const float* bet   = (const float*)d_in[9];
    const float* mu    = (const float*)d_in[10];
    const float* va    = (const float*)d_in[11];

    // driver entry point (runtime-resolved; no -lcuda)
    void* fp = nullptr;
    cudaDriverEntryPointQueryResult qr;
#if CUDART_VERSION >= 12050
    cudaGetDriverEntryPointByVersion("cuTensorMapEncodeTiled", &fp, 12000,
                                     cudaEnableDefault, &qr);
#else
    cudaGetDriverEntryPoint("cuTensorMapEncodeTiled", &fp, cudaEnableDefault, &qr);
#endif
    EncFn enc = (EncFn)fp;

    void *px, *pb1, *pb2;
    cudaGetSymbolAddress(&px,  g_x16);
    cudaGetSymbolAddress(&pb1, g_buf1);
    cudaGetSymbolAddress(&pb2, g_buf2);

    constexpr int R1 = TILER + 2, C1 = TILEC + 2;     // D=1
    constexpr int R2 = TILER + 4, C2 = TILEC + 4;     // D=2
    CUtensorMap tmX, tmB1, tmB2;
    encode_map(enc, &tmX,  px,  MAPH, MAPH, NBATCH,       MAPH, C1, R1);
    encode_map(enc, &tmB1, pb1, BSTR, BSTR, NBR * NBATCH, BSTR, C2, R2);
    encode_map(enc, &tmB2, pb2, BSTR, BSTR, NBR * NBATCH, BSTR, C2, R2);

    constexpr int PAT1 = ((R1 * C1 * 128 + 1023) & ~1023);
    constexpr int PAT2 = ((R2 * C2 * 128 + 1023) & ~1023);
    constexpr int SMEM_D1 = 1024 + WBYTES + 2 * PAT1 + 16 + 256;
    constexpr int SMEM_D2 = 1024 + WBYTES + 2 * PAT2 + 16 + 256;

    cudaFuncSetAttribute((const void*)conv_mma<1, 1>,
                         cudaFuncAttributeMaxDynamicSharedMemorySize, SMEM_D1);
    cudaFuncSetAttribute((const void*)conv_mma<2, 2>,
                         cudaFuncAttributeMaxDynamicSharedMemorySize, SMEM_D2);
    cudaFuncSetAttribute((const void*)conv_mma<2, 3>,
                         cudaFuncAttributeMaxDynamicSharedMemorySize, SMEM_D2);

    cvt_x<<<NBATCH * (MAPH * MAPH / 64), 256>>>(x);

    const int prepN = 16 * WSETW + 192;
    prep_kernel<<<(prepN + 255) / 256, 256>>>(dcn_w, dcn_b, c2w, c2b, c3w, c3b,
                                              gam, bet, mu, va);

    // Stage 1: even 96 (4x6 tiles), odd 104 (5x7)
    conv_mma<1, 1><<<dim3(5, NBATCH, NBR), 256, SMEM_D1>>>(tmX);
    // Stage 2: even 96, odd 100 (5x7)
    conv_mma<2, 2><<<dim3(5, NBATCH, NBR), 256, SMEM_D2>>>(tmB1);
    // Stage 3: 96 exact (4x6)
    conv_mma<2, 3><<<dim3(4, NBATCH, NBR), 256, SMEM_D2>>>(tmB2);

    final_k<<<(NBATCH * MAPH * MAPH + 255) / 256, 256>>>((float*)d_out);
}

// round 13
// speedup vs baseline: 1.1647x; 1.0681x over previous
#include <cuda_runtime.h>
#include <cuda_fp16.h>
#include <cuda.h>
#include <cstdint>
#include <math.h>

#define NBATCH 8
#define NCH    64
#define MAPH   96
#define NBR    8
#define BSTR   104
#define BCHS   (BSTR*BSTR)
#define WSETW  18432
#define WBYTES 73728
#define TILER  24
#define TILEC  16
#define NCTA   148

// channel-last fp16 activations, pixel stride 128B. Zero-init halos are
// load-bearing: TMA reads of never-written regions must return 0.
__device__ __align__(1024) __half g_x16[(size_t)NBATCH*MAPH*MAPH*NCH];
__device__ __align__(1024) __half g_buf1[(size_t)NBR*NBATCH*BCHS*NCH];
__device__ __align__(1024) __half g_buf2[(size_t)NBR*NBATCH*BCHS*NCH];
__device__ float  g_bmax[NBR*NBATCH*MAPH*MAPH];
__device__ __align__(16) uint32_t g_w1[8*WSETW];
__device__ __align__(16) uint32_t g_w2[4*WSETW];
__device__ __align__(16) uint32_t g_w3[4*WSETW];
__device__ float g_bias[3*64];

__device__ __forceinline__ void rotmap(int k, int A, int B, int& sa, int& sb) {
    switch (k & 3) {
        case 0: sa = A;     sb = B;     break;
        case 1: sa = 2 - B; sb = A;     break;
        case 2: sa = 2 - A; sb = 2 - B; break;
        default: sa = B;    sb = 2 - A; break;
    }
}
__device__ __forceinline__ uint32_t smem_u32(const void* p) {
    uint32_t a;
    asm("{ .reg .u64 t; cvta.to.shared.u64 t, %1; cvt.u32.u64 %0, t; }"
        : "=r"(a) : "l"(p));
    return a;
}
__device__ __forceinline__ void mma_f16(float& c0, float& c1, float& c2, float& c3,
                                        uint32_t a0, uint32_t a1, uint32_t a2, uint32_t a3,
                                        uint32_t b0, uint32_t b1) {
    asm volatile(
        "mma.sync.aligned.m16n8k16.row.col.f32.f16.f16.f32 "
        "{%0,%1,%2,%3}, {%4,%5,%6,%7}, {%8,%9}, {%0,%1,%2,%3};"
        : "+f"(c0), "+f"(c1), "+f"(c2), "+f"(c3)
        : "r"(a0), "r"(a1), "r"(a2), "r"(a3), "r"(b0), "r"(b1));
}
__device__ __forceinline__ void ldmatrix_x4(uint32_t& r0, uint32_t& r1,
                                            uint32_t& r2, uint32_t& r3, uint32_t addr) {
    asm volatile("ldmatrix.sync.aligned.m8n8.x4.shared.b16 {%0,%1,%2,%3}, [%4];"
                 : "=r"(r0), "=r"(r1), "=r"(r2), "=r"(r3) : "r"(addr));
}
__device__ __forceinline__ void tma4d(uint32_t dst, const CUtensorMap* m,
                                      int cx, int cy, int img, uint32_t mbar) {
    asm volatile(
        "cp.async.bulk.tensor.4d.shared::cta.global.tile.mbarrier::complete_tx::bytes "
        "[%0], [%1, {%2, %3, %4, %5}], [%6];"
        :: "r"(dst), "l"(m), "r"(0), "r"(cx), "r"(cy), "r"(img), "r"(mbar)
        : "memory");
}
#define MBAR_INIT(a, n) \
    asm volatile("mbarrier.init.shared.b64 [%0], %1;" :: "r"(a), "r"(n) : "memory")
#define MBAR_EXPECT(a, bytes) \
    asm volatile("mbarrier.arrive.expect_tx.shared.b64 _, [%0], %1;" \
                 :: "r"(a), "r"(bytes) : "memory")
__device__ __forceinline__ void mbar_wait(uint32_t a, uint32_t ph) {
    uint32_t done;
    asm volatile("{\n\t.reg .pred p;\n\t"
        "mbarrier.try_wait.parity.acquire.cta.shared::cta.b64 p, [%1], %2;\n\t"
        "selp.b32 %0, 1, 0, p;\n\t}" : "=r"(done) : "r"(a), "r"(ph) : "memory");
    if (!done) {
        asm volatile("{\n\t.reg .pred P1;\n\t"
            "WL_%=:\n\t"
            "mbarrier.try_wait.parity.acquire.cta.shared::cta.b64 P1, [%0], %1, 0x989680;\n\t"
            "@P1 bra.uni WD_%=;\n\t"
            "bra.uni WL_%=;\n\t"
            "WD_%=:\n\t}" :: "r"(a), "r"(ph) : "memory");
    }
}

// ---------------------------------------------------------------------------
__global__ void cvt_x(const float* __restrict__ x)
{
    __shared__ float t[64][65];
    const int NPB = MAPH * MAPH;
    const int b = blockIdx.x / (NPB / 64);
    const int pix0 = (blockIdx.x % (NPB / 64)) * 64;
    const float* src = x + (size_t)b * NCH * NPB;
    for (int i = threadIdx.x; i < 4096; i += 256) {
        int ic = i >> 6, px = i & 63;
        t[px][ic] = src[ic * NPB + pix0 + px];
    }
    __syncthreads();
    __half* dst = g_x16 + ((size_t)b * NPB + pix0) * NCH;
    for (int i = threadIdx.x; i < 4096; i += 256) {
        int px = i >> 6, ic = i & 63;
        dst[px * 64 + ic] = __float2half(t[px][ic]);
    }
}

// ---------------------------------------------------------------------------
__global__ void prep_kernel(
    const float* __restrict__ dcn_w, const float* __restrict__ dcn_b,
    const float* __restrict__ c2w,   const float* __restrict__ c2b,
    const float* __restrict__ c3w,   const float* __restrict__ c3b,
    const float* __restrict__ gam,   const float* __restrict__ bet,
    const float* __restrict__ mu,    const float* __restrict__ va)
{
    int id = blockIdx.x * blockDim.x + threadIdx.x;
    const int W1N = 8 * WSETW, W2N = 4 * WSETW;

    if (id < W1N + 2 * W2N) {
        int setBase;
        uint32_t* dst;
        const float* src;
        int bnOff;
        if (id < W1N)            { dst = g_w1; src = dcn_w; bnOff = 0;   setBase = id; }
        else if (id < W1N + W2N) { dst = g_w2; src = c2w;   bnOff = 64;  setBase = id - W1N; }
        else                     { dst = g_w3; src = c3w;   bnOff = 128; setBase = id - W1N - W2N; }
        int set = setBase / WSETW;
        int e   = setBase % WSETW;
        int r    = e & 1;
        int half = (e >> 1) & 1;
        int lane = (e >> 2) & 31;
        int np   = (e >> 7) & 3;
        int k16  = (e >> 9) & 3;
        int tap  = e >> 11;
        int nt = np * 2 + half;
        int oc  = nt * 8 + (lane >> 2);
        int ic0 = k16 * 16 + 2 * (lane & 3) + 8 * r;
        int sa, sb; rotmap(set & 3, tap / 3, tap % 3, sa, sb);
        float scale = gam[bnOff + oc] * rsqrtf(va[bnOff + oc] + 1e-5f);
        int sc0 = (bnOff == 0) ? ((ic0 + 8 * set) & 63) : ic0;
        int sc1 = (bnOff == 0) ? ((ic0 + 1 + 8 * set) & 63) : (ic0 + 1);
        float v0 = src[((oc * 64 + sc0) * 3 + sa) * 3 + sb] * scale;
        float v1 = src[((oc * 64 + sc1) * 3 + sa) * 3 + sb] * scale;
        dst[setBase] = (uint32_t)__half_as_ushort(__float2half(v0))
                     | ((uint32_t)__half_as_ushort(__float2half(v1)) << 16);
        return;
    }
    id -= W1N + 2 * W2N;
    if (id < 192) {
        int s = id / 64, oc = id & 63;
        float scale = gam[s * 64 + oc] * rsqrtf(va[s * 64 + oc] + 1e-5f);
        const float* cb = (s == 0) ? dcn_b : ((s == 1) ? c2b : c3b);
        g_bias[id] = cb[oc] * scale + bet[s * 64 + oc] - mu[s * 64 + oc] * scale;
    }
}

// ---------------------------------------------------------------------------
// Tile decode: branch-major flattened tile list.
// Stage 1/2: even branches 24 tiles/pair (4rt x 6ct), odd 35 (5rt x 7ct).
// Stage 3: all branches 24 tiles/pair.
// ---------------------------------------------------------------------------
template<int STAGE>
__device__ __forceinline__ void decode_tile(int i, int& br, int& b, int& rt, int& ct)
{
    if (STAGE == 3) {
        br = i / 192; int r = i % 192;
        b = r / 24; r %= 24; rt = r / 6; ct = r % 6;
    } else {
        if (i < 768) {
            br = 2 * (i / 192); int r = i % 192;
            b = r / 24; r %= 24; rt = r / 6; ct = r % 6;
        } else {
            i -= 768;
            br = 2 * (i / 280) + 1; int r = i % 280;
            b = r / 35; r %= 35; rt = r / 7; ct = r % 7;
        }
    }
}

// ---------------------------------------------------------------------------
// Conv: fp16 mma implicit GEMM, TMA double-buffered, persistent chunks.
// 148 CTAs; CTA c handles contiguous tile chunk [c*nT/148, (c+1)*nT/148).
// 256 thr = 8 warps; warp w owns tile rows 3w..3w+2 x 64 oc. Tile 24x16.
// ---------------------------------------------------------------------------
template<int D, int STAGE>
__global__ void __launch_bounds__(256, 1)
conv_mma(const __grid_constant__ CUtensorMap tmap)
{
    constexpr int R = TILER + 2 * D;
    constexpr int C = TILEC + 2 * D;
    constexpr int PATB = R * C * 128;
    constexpr int PATB_AL = (PATB + 1023) & ~1023;
    constexpr int OFF_B0 = WBYTES;
    constexpr int OFF_B1 = WBYTES + PATB_AL;
    constexpr int OFF_MB = WBYTES + 2 * PATB_AL;
    constexpr int OFF_BIAS = OFF_MB + 16;
    constexpr int NT = (STAGE == 3) ? 1536 : 1888;

    extern __shared__ char sm[];
    const uint32_t raw = smem_u32(sm);
    const uint32_t base = (raw + 1023) & ~1023u;
    char* smc = sm + (base - raw);
    uint32_t* sW = (uint32_t*)smc;
    float* sBias = (float*)(smc + OFF_BIAS);

    const int tid  = threadIdx.x;
    const int lane = tid & 31;
    const int wid  = tid >> 5;

    const int c = blockIdx.x;
    const int i0 = (c * NT) / NCTA;
    const int i1 = ((c + 1) * NT) / NCTA;
    if (i0 >= i1) return;

    const uint32_t* wbase = (STAGE == 1) ? g_w1 : (STAGE == 2) ? g_w2 : g_w3;
    __half* obase = (STAGE == 1) ? g_buf1 : g_buf2;

    // ---- init: bias, mbarriers, first tile's weights, first TMA ----
    int br0, b0, rt0, ct0;
    decode_tile<STAGE>(i0, br0, b0, rt0, ct0);
    const int wsel0 = (STAGE == 1) ? br0 : (br0 & 3);
    {
        uint4* wd = (uint4*)sW;
        const uint4* ws = (const uint4*)(wbase + wsel0 * WSETW);
        #pragma unroll 4
        for (int i = tid; i < WSETW / 4; i += 256) wd[i] = ws[i];
        if (tid < 64) sBias[tid] = g_bias[(STAGE - 1) * 64 + tid];
        if (tid == 0) { MBAR_INIT(base + OFF_MB, 1); MBAR_INIT(base + OFF_MB + 8, 1); }
    }
    __syncthreads();

    const int g  = lane >> 2;
    const int t4 = lane & 3;
    const uint32_t bufU[2] = { base + OFF_B0, base + OFF_B1 };
    const uint32_t mbU[2]  = { base + OFF_MB, base + OFF_MB + 8 };
    const int ccol = lane & 15;
    const int khalf16 = (lane >> 4) * 16;

    uint32_t ph[2] = {0, 0};
    int prevWsel = wsel0;

    // preload tile i0
    {
        const int padF = (STAGE == 1) ? ((br0 & 1) ? 5 : 1) : ((br0 & 1) ? 0 : 2);
        const int imgF = (STAGE == 1) ? b0 : (br0 * NBATCH + b0);
        if (tid == 0) {
            MBAR_EXPECT(mbU[0], PATB);
            tma4d(bufU[0], &tmap, ct0 * TILEC - padF, rt0 * TILER - padF, imgF, mbU[0]);
        }
    }

    for (int idx = i0; idx < i1; idx++) {
        const int s = (idx - i0) & 1;
        int br, b, rt, ct;
        decode_tile<STAGE>(idx, br, b, rt, ct);
        const int odd = br & 1;
        const int pad  = (STAGE == 1) ? (odd ? 5 : 1) : (odd ? 0 : 2);
        const int outH = (STAGE == 1) ? (odd ? 104 : 96)
                        : (STAGE == 2) ? (odd ? 100 : 96) : 96;
        const int outW = outH;
        const int rowBase = rt * TILER;
        const int colBase = ct * TILEC;

        // prefetch tile idx+1
        if (idx + 1 < i1 && tid == 0) {
            int nbr, nb, nrt, nct;
            decode_tile<STAGE>(idx + 1, nbr, nb, nrt, nct);
            const int npad = (STAGE == 1) ? ((nbr & 1) ? 5 : 1) : ((nbr & 1) ? 0 : 2);
            const int nimg = (STAGE == 1) ? nb : (nbr * NBATCH + nb);
            MBAR_EXPECT(mbU[s ^ 1], PATB);
            tma4d(bufU[s ^ 1], &tmap, nct * TILEC - npad, nrt * TILER - npad,
                  nimg, mbU[s ^ 1]);
        }

        // weight reload on branch-set change (uniform across block)
        const int wsel = (STAGE == 1) ? br : (br & 3);
        if (wsel != prevWsel) {
            __syncthreads();   // prior GEMM reads of sW complete
            uint4* wd = (uint4*)sW;
            const uint4* ws = (const uint4*)(wbase + wsel * WSETW);
            #pragma unroll 4
            for (int i = tid; i < WSETW / 4; i += 256) wd[i] = ws[i];
            __syncthreads();
            prevWsel = wsel;
        }

        mbar_wait(mbU[s], ph[s]); ph[s] ^= 1;

        float acc[3][8][4];
        #pragma unroll
        for (int mt = 0; mt < 3; mt++)
            #pragma unroll
            for (int nt = 0; nt < 8; nt++)
                #pragma unroll
                for (int q = 0; q < 4; q++) acc[mt][nt][q] = 0.f;

        const uint32_t bU = bufU[s];

        #pragma unroll 1
        for (int tap = 0; tap < 9; tap++) {
            const int dyD = (tap / 3) * D, dxD = (tap % 3) * D;
            uint32_t aP[3], swm[3];
            #pragma unroll
            for (int mt = 0; mt < 3; mt++) {
                const int p = (wid * 3 + mt + dyD) * C + ccol + dxD;
                aP[mt] = bU + (uint32_t)(p << 7);
                swm[mt] = (uint32_t)((p & 7) << 4);
            }
            const uint4* pB = (const uint4*)sW + (tap * 16) * 32 + lane;

            #pragma unroll
            for (int k16 = 0; k16 < 4; k16++) {
                const uint32_t kofs = k16 * 32 + khalf16;
                uint32_t a[3][4];
                #pragma unroll
                for (int mt = 0; mt < 3; mt++)
                    ldmatrix_x4(a[mt][0], a[mt][1], a[mt][2], a[mt][3],
                                aP[mt] + (kofs ^ swm[mt]));
                const uint4* pBk = pB + (k16 * 4) * 32;
                #pragma unroll
                for (int np = 0; np < 4; np++) {
                    uint4 bb = pBk[np * 32];
                    #pragma unroll
                    for (int mt = 0; mt < 3; mt++) {
                        mma_f16(acc[mt][2*np][0], acc[mt][2*np][1],
                                acc[mt][2*np][2], acc[mt][2*np][3],
                                a[mt][0], a[mt][1], a[mt][2], a[mt][3], bb.x, bb.y);
                        mma_f16(acc[mt][2*np+1][0], acc[mt][2*np+1][1],
                                acc[mt][2*np+1][2], acc[mt][2*np+1][3],
                                a[mt][0], a[mt][1], a[mt][2], a[mt][3], bb.z, bb.w);
                    }
                }
            }
        }

        // ---- epilogue ----
        __half* outp = obase + (size_t)(br * NBATCH + b) * BCHS * NCH;
        if (STAGE < 3) {
            #pragma unroll
            for (int mt = 0; mt < 3; mt++) {
                const int oy = rowBase + wid * 3 + mt;
                if (oy >= outH) continue;
                const int ox0 = colBase + g;
                const int ox1 = ox0 + 8;
                #pragma unroll
                for (int nt = 0; nt < 8; nt++) {
                    const int oc = nt * 8 + 2 * t4;
                    const float b0f = sBias[oc], b1f = sBias[oc + 1];
                    if (ox0 < outW) {
                        float2 f = make_float2(fmaxf(acc[mt][nt][0] + b0f, 0.f),
                                               fmaxf(acc[mt][nt][1] + b1f, 0.f));
                        *(__half2*)(outp + (size_t)(oy * BSTR + ox0) * 64 + oc) =
                            __float22half2_rn(f);
                    }
                    if (ox1 < outW) {
                        float2 f = make_float2(fmaxf(acc[mt][nt][2] + b0f, 0.f),
                                               fmaxf(acc[mt][nt][3] + b1f, 0.f));
                        *(__half2*)(outp + (size_t)(oy * BSTR + ox1) * 64 + oc) =
                            __float22half2_rn(f);
                    }
                }
            }
        } else {
            float* bm = g_bmax + (size_t)(br * NBATCH + b) * MAPH * MAPH;
            #pragma unroll
            for (int mt = 0; mt < 3; mt++) {
                const int oy = rowBase + wid * 3 + mt;
                float v0 = 0.f, v1 = 0.f;
                #pragma unroll
                for (int nt = 0; nt < 8; nt++) {
                    const int oc = nt * 8 + 2 * t4;
                    const float b0f = sBias[oc], b1f = sBias[oc + 1];
                    v0 = fmaxf(v0, fmaxf(acc[mt][nt][0] + b0f, acc[mt][nt][1] + b1f));
                    v1 = fmaxf(v1, fmaxf(acc[mt][nt][2] + b0f, acc[mt][nt][3] + b1f));
                }
                v0 = fmaxf(v0, __shfl_xor_sync(0xFFFFFFFF, v0, 1));
                v0 = fmaxf(v0, __shfl_xor_sync(0xFFFFFFFF, v0, 2));
                v1 = fmaxf(v1, __shfl_xor_sync(0xFFFFFFFF, v1, 1));
                v1 = fmaxf(v1, __shfl_xor_sync(0xFFFFFFFF, v1, 2));
                if (t4 == 0 && oy < MAPH) {
                    const int ox0 = colBase + g;
                    if (ox0 < MAPH)     bm[oy * MAPH + ox0]     = v0;
                    if (ox0 + 8 < MAPH) bm[oy * MAPH + ox0 + 8] = v1;
                }
            }
        }

        __syncthreads();   // slot s fully read before refill at idx+2
    }
}

// ---------------------------------------------------------------------------
__global__ void final_k(float* __restrict__ out)
{
    int i = blockIdx.x * blockDim.x + threadIdx.x;
    const int NPB = MAPH * MAPH;
    if (i >= NBATCH * NPB) return;
    int b = i / NPB, p = i - b * NPB;
    float m = g_bmax[b * NPB + p];
    #pragma unroll
    for (int br = 1; br < NBR; br++)
        m = fmaxf(m, g_bmax[(br * NBATCH + b) * NPB + p]);
    float s = 1.f / (1.f + expf(-m));
    out[i] = fminf(fmaxf(s, 0.0001f), 0.9999f);
}

// ---------------------------------------------------------------------------
// Host: tensor-map encoding + launch
// ---------------------------------------------------------------------------
typedef CUresult (*EncFn)(CUtensorMap*, CUtensorMapDataType, cuuint32_t, void*,
                          const cuuint64_t*, const cuuint64_t*, const cuuint32_t*,
                          const cuuint32_t*, CUtensorMapInterleave, CUtensorMapSwizzle,
                          CUtensorMapL2promotion, CUtensorMapFloatOOBfill);

static void encode_map(EncFn enc, CUtensorMap* m, void* ptr,
                       int dimX, int dimY, int nImg, int strideX,
                       int boxC, int boxR)
{
    cuuint64_t dims[4]    = { 128, (cuuint64_t)dimX, (cuuint64_t)dimY, (cuuint64_t)nImg };
    cuuint64_t strides[3] = { 128, (cuuint64_t)strideX * 128,
                              (cuuint64_t)strideX * (cuuint64_t)dimY * 128 };
    cuuint32_t box[4]     = { 128, (cuuint32_t)boxC, (cuuint32_t)boxR, 1 };
    cuuint32_t es[4]      = { 1, 1, 1, 1 };
    enc(m, CU_TENSOR_MAP_DATA_TYPE_UINT8, 4, ptr, dims, strides, box, es,
        CU_TENSOR_MAP_INTERLEAVE_NONE, CU_TENSOR_MAP_SWIZZLE_128B,
        CU_TENSOR_MAP_L2_PROMOTION_L2_128B, CU_TENSOR_MAP_FLOAT_OOB_FILL_NONE);
}

extern "C" void kernel_launch(void* const* d_in, const int* in_sizes, int n_in,
                              void* d_out, int out_size)
{
    const float* x     = (const float*)d_in[0];
    const float* dcn_w = (const float*)d_in[2];
    const float* dcn_b = (const float*)d_in[3];
    const float* c2w   = (const float*)d_in[4];
    const float* c2b   = (const float*)d_in[5];
    const float* c3w   = (const float*)d_in[6];
    const float* c3b   = (const float*)d_in[7];
    const float* gam   = (const float*)d_in[8];
    const float* bet   = (const float*)d_in[9];
    const float* mu    = (const float*)d_in[10];
    const float* va    = (const float*)d_in[11];

    void* fp = nullptr;
    cudaDriverEntryPointQueryResult qr;
#if CUDART_VERSION >= 12050
    cudaGetDriverEntryPointByVersion("cuTensorMapEncodeTiled", &fp, 12000,
                                     cudaEnableDefault, &qr);
#else
    cudaGetDriverEntryPoint("cuTensorMapEncodeTiled", &fp, cudaEnableDefault, &qr);
#endif
    EncFn enc = (EncFn)fp;

    void *px, *pb1, *pb2;
    cudaGetSymbolAddress(&px,  g_x16);
    cudaGetSymbolAddress(&pb1, g_buf1);
    cudaGetSymbolAddress(&pb2, g_buf2);

    constexpr int R1 = TILER + 2, C1 = TILEC + 2;     // D=1
    constexpr int R2 = TILER + 4, C2 = TILEC + 4;     // D=2
    CUtensorMap tmX, tmB1, tmB2;
    encode_map(enc, &tmX,  px,  MAPH, MAPH, NBATCH,       MAPH, C1, R1);
    encode_map(enc, &tmB1, pb1, BSTR, BSTR, NBR * NBATCH, BSTR, C2, R2);
    encode_map(enc, &tmB2, pb2, BSTR, BSTR, NBR * NBATCH, BSTR, C2, R2);

    constexpr int PAT1 = ((R1 * C1 * 128 + 1023) & ~1023);
    constexpr int PAT2 = ((R2 * C2 * 128 + 1023) & ~1023);
    constexpr int SMEM_D1 = 1024 + WBYTES + 2 * PAT1 + 16 + 256;
    constexpr int SMEM_D2 = 1024 + WBYTES + 2 * PAT2 + 16 + 256;

    cudaFuncSetAttribute((const void*)conv_mma<1, 1>,
                         cudaFuncAttributeMaxDynamicSharedMemorySize, SMEM_D1);
    cudaFuncSetAttribute((const void*)conv_mma<2, 2>,
                         cudaFuncAttributeMaxDynamicSharedMemorySize, SMEM_D2);
    cudaFuncSetAttribute((const void*)conv_mma<2, 3>,
                         cudaFuncAttributeMaxDynamicSharedMemorySize, SMEM_D2);

    cvt_x<<<NBATCH * (MAPH * MAPH / 64), 256>>>(x);

    const int prepN = 16 * WSETW + 192;
    prep_kernel<<<(prepN + 255) / 256, 256>>>(dcn_w, dcn_b, c2w, c2b, c3w, c3b,
                                              gam, bet, mu, va);

    conv_mma<1, 1><<<NCTA, 256, SMEM_D1>>>(tmX);
    conv_mma<2, 2><<<NCTA, 256, SMEM_D2>>>(tmB1);
    conv_mma<2, 3><<<NCTA, 256, SMEM_D2>>>(tmB2);

    final_k<<<(NBATCH * MAPH * MAPH + 255) / 256, 256>>>((float*)d_out);
}